// round 14
// baseline (speedup 1.0000x reference)
#include <cuda_runtime.h>
#include <cuda_fp16.h>
#include <cstdint>

#define N_USERS  100000
#define M_ITEMS  50000
#define N_ALL    150000
#define N_EDGES  4800000
#define DIM      64
#define NELEM    (N_ALL * DIM)

// Jacobi coefficients for A=B=1
#define THETA1_K2 1.875f
#define THETA3_K2 0.75f
#define THETA1_K3 (28.0f / 15.0f)

#define SCAN_BLK 1024
#define N_SCAN_BLOCKS ((N_ALL + SCAN_BLK - 1) / SCAN_BLK)   // 147

#define RPB   8        // rows per block (8 warps)
#define STAGE 512      // staged epack entries (4 KB smem); E[edges/block]=256

// Static scratch (allocation-free rule)
__device__ __align__(16) float  g_embed[NELEM];   // fp32 embed
__device__ __align__(16) float  g_e2f[NELEM];     // fp32 e2 (epilogue operand)
__device__ __align__(16) __half g_hx[3][NELEM];   // fp16 gather shadows: embed,e1,e2
__device__ int   g_count[N_ALL];                  // zero-invariant between calls
__device__ int   g_start[N_ALL + 1];
__device__ int   g_cursor[N_ALL];
__device__ __align__(8) int2 g_epack[N_EDGES];    // (col, val-bits) CSR-ordered
__device__ int   g_bsum[N_SCAN_BLOCKS];

// L2-only load for streamed (zero-reuse) data
__device__ __forceinline__ int2 ldcg_int2(const int2* p) {
    int2 r;
    asm volatile("ld.global.cg.v2.u32 {%0, %1}, [%2];"
                 : "=r"(r.x), "=r"(r.y) : "l"(p));
    return r;
}

// ---------------------------------------------------------------------------
// init: embed = concat(user,item) fp32 + fp16 shadow; fused row histogram
// ---------------------------------------------------------------------------
__global__ void init_kernel(const float* __restrict__ user,
                            const float* __restrict__ item,
                            const int*   __restrict__ rows) {
    int i = blockIdx.x * blockDim.x + threadIdx.x;   // float4 index
    const int n4 = NELEM / 4;                        // 2,400,000
    if (i < n4) {
        float4 v;
        if (i < (N_USERS * DIM) / 4)
            v = ((const float4*)user)[i];
        else
            v = ((const float4*)item)[i - (N_USERS * DIM) / 4];
        ((float4*)g_embed)[i] = v;
        __half2 h0 = __floats2half2_rn(v.x, v.y);
        __half2 h1 = __floats2half2_rn(v.z, v.w);
        ((__half2*)g_hx[0])[2 * i]     = h0;
        ((__half2*)g_hx[0])[2 * i + 1] = h1;
        atomicAdd(&g_count[__ldg(rows + i)], 1);
        atomicAdd(&g_count[__ldg(rows + i + n4)], 1);
    }
}

// ---------------------------------------------------------------------------
// scan stage 1: per-block exclusive scan of counts; re-zero counts
// ---------------------------------------------------------------------------
__global__ void scan1_kernel() {
    __shared__ int sh[SCAN_BLK];
    int t = threadIdx.x;
    int i = blockIdx.x * SCAN_BLK + t;
    int v = (i < N_ALL) ? g_count[i] : 0;
    if (i < N_ALL) g_count[i] = 0;
    sh[t] = v;
    __syncthreads();
    for (int o = 1; o < SCAN_BLK; o <<= 1) {
        int a = (t >= o) ? sh[t - o] : 0;
        __syncthreads();
        sh[t] += a;
        __syncthreads();
    }
    if (i < N_ALL) g_start[i] = sh[t] - v;
    if (t == SCAN_BLK - 1) g_bsum[blockIdx.x] = sh[t];
}

// scan stage 2: parallel exclusive scan of 147 block sums
__global__ void scan2_kernel() {
    __shared__ int sh[256];
    int t = threadIdx.x;
    int v = (t < N_SCAN_BLOCKS) ? g_bsum[t] : 0;
    sh[t] = v;
    __syncthreads();
    for (int o = 1; o < 256; o <<= 1) {
        int a = (t >= o) ? sh[t - o] : 0;
        __syncthreads();
        sh[t] += a;
        __syncthreads();
    }
    if (t < N_SCAN_BLOCKS) g_bsum[t] = sh[t] - v;
}

// scan stage 3: add block offsets; init cursors; sentinel
__global__ void scan3_kernel() {
    int i = blockIdx.x * SCAN_BLK + threadIdx.x;
    if (i < N_ALL) {
        int s = g_start[i] + g_bsum[blockIdx.x];
        g_start[i]  = s;
        g_cursor[i] = s;
    }
    if (i == 0) g_start[N_ALL] = N_EDGES;
}

// ---------------------------------------------------------------------------
// scatter edges into CSR order
// ---------------------------------------------------------------------------
__global__ void scatter_kernel(const int*   __restrict__ rows,
                               const int*   __restrict__ cols,
                               const float* __restrict__ vals) {
    int e = blockIdx.x * blockDim.x + threadIdx.x;
    if (e >= N_EDGES) return;
    int r = __ldg(rows + e);
    int pos = atomicAdd(&g_cursor[r], 1);
    g_epack[pos] = make_int2(__ldg(cols + e), __float_as_int(__ldg(vals + e)));
}

// ---------------------------------------------------------------------------
// SpMM core with block-staged epack:
//   block = 8 warps = rows [8b, 8b+8); the block's CSR edge range is
//   contiguous -> cooperatively stage it into smem (coalesced), then each
//   warp reads its row's entries via LDS (29 cyc) instead of L2 (~250 cyc).
//   Lane layout unchanged: 8 lanes per edge (16 B each), lane = g*8+sl.
// ---------------------------------------------------------------------------
__device__ __forceinline__ void edge_accum(const __half* __restrict__ hx,
                                           int2 p, int sl, float acc[8]) {
    float v = __int_as_float(p.y);
    uint4 q = __ldg((const uint4*)(hx + (size_t)p.x * DIM) + sl);
    float2 f;
    f = __half22float2(*(__half2*)&q.x); acc[0] += v * f.x; acc[1] += v * f.y;
    f = __half22float2(*(__half2*)&q.y); acc[2] += v * f.x; acc[3] += v * f.y;
    f = __half22float2(*(__half2*)&q.z); acc[4] += v * f.x; acc[5] += v * f.y;
    f = __half22float2(*(__half2*)&q.w); acc[6] += v * f.x; acc[7] += v * f.y;
}

// windowed accumulation over the block's contiguous edge range
__device__ __forceinline__ void spmm_staged(const __half* __restrict__ hx,
                                            int2* se,
                                            int blk_s, int blk_e,
                                            int rs, int re,
                                            int tid, int g, int sl,
                                            float acc[8]) {
#pragma unroll
    for (int k = 0; k < 8; k++) acc[k] = 0.f;
    for (int win = blk_s; win < blk_e; win += STAGE) {
        int wend = min(win + STAGE, blk_e);
        if (win != blk_s) __syncthreads();           // smem reuse barrier
        for (int k = win + tid; k < wend; k += 256)
            se[k - win] = ldcg_int2(&g_epack[k]);    // coalesced stage-in
        __syncthreads();
        int a = rs > win  ? rs : win;
        int b = re < wend ? re : wend;
        if (a < b) {
            int n4 = (b - a) & ~3;
#pragma unroll 2
            for (int j = a; j < a + n4; j += 4) {
                int2 p = se[j - win + g];            // LDS, 4 distinct 8B addrs
                edge_accum(hx, p, sl, acc);
            }
            int rem = (b - a) - n4;
            if (g < rem) {
                int2 p = se[a + n4 - win + g];
                edge_accum(hx, p, sl, acc);
            }
        }
    }
#pragma unroll
    for (int k = 0; k < 8; k++) {
        acc[k] += __shfl_xor_sync(0xFFFFFFFFu, acc[k], 8);
        acc[k] += __shfl_xor_sync(0xFFFFFFFFu, acc[k], 16);
    }
}

__device__ __forceinline__ uint4 pack_half8(const float a[8]) {
    __half2 h[4];
    h[0] = __floats2half2_rn(a[0], a[1]);
    h[1] = __floats2half2_rn(a[2], a[3]);
    h[2] = __floats2half2_rn(a[4], a[5]);
    h[3] = __floats2half2_rn(a[6], a[7]);
    return *(uint4*)h;
}

// shared prolog for the staged SpMM kernels
#define STAGED_PROLOG                                                     \
    __shared__ int2 se[STAGE];                                            \
    __shared__ int  sst[RPB + 1];                                         \
    int tid  = threadIdx.x;                                               \
    int warp = tid >> 5;                                                  \
    int lane = tid & 31;                                                  \
    int g = lane >> 3, sl = lane & 7;                                     \
    int base = blockIdx.x * RPB;                                          \
    if (tid <= RPB) sst[tid] = g_start[base + tid];                       \
    __syncthreads();                                                      \
    int blk_s = sst[0], blk_e = sst[RPB];                                 \
    int rs = sst[warp], re = sst[warp + 1];                               \
    int w = base + warp;                                                  \
    float acc[8];

// spmm1: e1 = spmm(embed) -> fp16 shadow
__global__ void __launch_bounds__(256) spmm1_kernel() {
    STAGED_PROLOG
    spmm_staged(g_hx[0], se, blk_s, blk_e, rs, re, tid, g, sl, acc);
    if (g == 0)
        ((uint4*)(g_hx[1] + (size_t)w * DIM))[sl] = pack_half8(acc);
}

// spmm2: e2 = 1.875*spmm(e1) - 0.75*embed -> fp16 shadow + fp32 copy
__global__ void __launch_bounds__(256) spmm2_kernel() {
    STAGED_PROLOG
    spmm_staged(g_hx[1], se, blk_s, blk_e, rs, re, tid, g, sl, acc);
    if (g < 2) {
        const float4* emp = (const float4*)(g_embed + (size_t)w * DIM);
        float4 em0 = emp[2 * sl], em1 = emp[2 * sl + 1];
        float r[8];
        r[0] = THETA1_K2 * acc[0] - THETA3_K2 * em0.x;
        r[1] = THETA1_K2 * acc[1] - THETA3_K2 * em0.y;
        r[2] = THETA1_K2 * acc[2] - THETA3_K2 * em0.z;
        r[3] = THETA1_K2 * acc[3] - THETA3_K2 * em0.w;
        r[4] = THETA1_K2 * acc[4] - THETA3_K2 * em1.x;
        r[5] = THETA1_K2 * acc[5] - THETA3_K2 * em1.y;
        r[6] = THETA1_K2 * acc[6] - THETA3_K2 * em1.z;
        r[7] = THETA1_K2 * acc[7] - THETA3_K2 * em1.w;
        if (g == 0) {
            ((uint4*)(g_hx[2] + (size_t)w * DIM))[sl] = pack_half8(r);
        } else {
            float4* e2p = (float4*)(g_e2f + (size_t)w * DIM);
            e2p[2 * sl]     = make_float4(r[0], r[1], r[2], r[3]);
            e2p[2 * sl + 1] = make_float4(r[4], r[5], r[6], r[7]);
        }
    }
}

// spmm3 + final epilogue:
//   bs = 0.25*(embed + 0.2*e1 + e2 + (28/15)*acc);  bp = tanh(0.1*embed - bs)
__global__ void __launch_bounds__(256) spmm3_kernel(float* __restrict__ out) {
    STAGED_PROLOG
    spmm_staged(g_hx[2], se, blk_s, blk_e, rs, re, tid, g, sl, acc);
    if (g < 2) {
        const float4* emp = (const float4*)(g_embed + (size_t)w * DIM);
        const float4* a2p = (const float4*)(g_e2f  + (size_t)w * DIM);
        float4 em0 = emp[2 * sl], em1 = emp[2 * sl + 1];
        float4 a20 = a2p[2 * sl], a21 = a2p[2 * sl + 1];
        uint4 a1q = ((const uint4*)(g_hx[1] + (size_t)w * DIM))[sl];
        float a1[8];
        {
            float2 f;
            f = __half22float2(*(__half2*)&a1q.x); a1[0] = f.x; a1[1] = f.y;
            f = __half22float2(*(__half2*)&a1q.y); a1[2] = f.x; a1[3] = f.y;
            f = __half22float2(*(__half2*)&a1q.z); a1[4] = f.x; a1[5] = f.y;
            f = __half22float2(*(__half2*)&a1q.w); a1[6] = f.x; a1[7] = f.y;
        }
        float em[8] = {em0.x, em0.y, em0.z, em0.w, em1.x, em1.y, em1.z, em1.w};
        float a2[8] = {a20.x, a20.y, a20.z, a20.w, a21.x, a21.y, a21.z, a21.w};
        float bs[8];
#pragma unroll
        for (int k = 0; k < 8; k++)
            bs[k] = 0.25f * (em[k] + 0.2f * a1[k] + a2[k] + THETA1_K3 * acc[k]);
        float4* orow = (float4*)(out + (size_t)w * 128);
        if (g == 0) {
            orow[2 * sl]     = make_float4(bs[0], bs[1], bs[2], bs[3]);
            orow[2 * sl + 1] = make_float4(bs[4], bs[5], bs[6], bs[7]);
        } else {
            float bp[8];
#pragma unroll
            for (int k = 0; k < 8; k++)
                bp[k] = tanhf(0.1f * em[k] - bs[k]);
            orow[16 + 2 * sl] = make_float4(bp[0], bp[1], bp[2], bp[3]);
            orow[17 + 2 * sl] = make_float4(bp[4], bp[5], bp[6], bp[7]);
        }
    }
}

// ---------------------------------------------------------------------------
extern "C" void kernel_launch(void* const* d_in, const int* in_sizes, int n_in,
                              void* d_out, int out_size) {
    const float* user = (const float*)d_in[0];
    const float* item = (const float*)d_in[1];
    const int*   rows = (const int*)d_in[2];
    const int*   cols = (const int*)d_in[3];
    const float* vals = (const float*)d_in[4];
    float* out = (float*)d_out;

    const int TPB = 256;
    const int init_blocks = (NELEM / 4 + TPB - 1) / TPB;
    const int edge_blocks = (N_EDGES + TPB - 1) / TPB;
    const int spmm_blocks = N_ALL / RPB;              // 18750

    init_kernel<<<init_blocks, TPB>>>(user, item, rows);
    scan1_kernel<<<N_SCAN_BLOCKS, SCAN_BLK>>>();
    scan2_kernel<<<1, 256>>>();
    scan3_kernel<<<N_SCAN_BLOCKS, SCAN_BLK>>>();
    scatter_kernel<<<edge_blocks, TPB>>>(rows, cols, vals);
    spmm1_kernel<<<spmm_blocks, TPB>>>();
    spmm2_kernel<<<spmm_blocks, TPB>>>();
    spmm3_kernel<<<spmm_blocks, TPB>>>(out);
}

// round 15
// speedup vs baseline: 1.0635x; 1.0635x over previous
#include <cuda_runtime.h>
#include <cuda_fp16.h>
#include <cstdint>

#define N_USERS  100000
#define M_ITEMS  50000
#define N_ALL    150000
#define N_EDGES  4800000
#define DIM      64
#define NELEM    (N_ALL * DIM)

// Jacobi coefficients for A=B=1
#define THETA1_K2 1.875f
#define THETA3_K2 0.75f
#define THETA1_K3 (28.0f / 15.0f)

#define SCAN_BLK 1024
#define N_SCAN_BLOCKS ((N_ALL + SCAN_BLK - 1) / SCAN_BLK)   // 147

// Static scratch (allocation-free rule)
__device__ __align__(16) float  g_embed[NELEM];   // fp32 embed
__device__ __align__(16) float  g_e2f[NELEM];     // fp32 e2 (epilogue operand)
__device__ __align__(16) __half g_hx[3][NELEM];   // fp16 gather shadows: embed,e1,e2
__device__ int   g_count[N_ALL];                  // zero-invariant between calls
__device__ int   g_start[N_ALL + 1];
__device__ int   g_cursor[N_ALL];
__device__ __align__(8) int2 g_epack[N_EDGES];    // (col, val-bits) CSR-ordered
__device__ int   g_bsum[N_SCAN_BLOCKS];

// ---------------------------------------------------------------------------
// init: embed = concat(user,item) fp32 + fp16 shadow; fused row histogram
// ---------------------------------------------------------------------------
__global__ void init_kernel(const float* __restrict__ user,
                            const float* __restrict__ item,
                            const int*   __restrict__ rows) {
    int i = blockIdx.x * blockDim.x + threadIdx.x;   // float4 index
    const int n4 = NELEM / 4;                        // 2,400,000
    if (i < n4) {
        float4 v;
        if (i < (N_USERS * DIM) / 4)
            v = ((const float4*)user)[i];
        else
            v = ((const float4*)item)[i - (N_USERS * DIM) / 4];
        ((float4*)g_embed)[i] = v;
        __half2 h0 = __floats2half2_rn(v.x, v.y);
        __half2 h1 = __floats2half2_rn(v.z, v.w);
        ((__half2*)g_hx[0])[2 * i]     = h0;
        ((__half2*)g_hx[0])[2 * i + 1] = h1;
        atomicAdd(&g_count[__ldg(rows + i)], 1);
        atomicAdd(&g_count[__ldg(rows + i + n4)], 1);
    }
}

// ---------------------------------------------------------------------------
// scan stage 1: per-block exclusive scan of counts; re-zero counts
// ---------------------------------------------------------------------------
__global__ void scan1_kernel() {
    __shared__ int sh[SCAN_BLK];
    int t = threadIdx.x;
    int i = blockIdx.x * SCAN_BLK + t;
    int v = (i < N_ALL) ? g_count[i] : 0;
    if (i < N_ALL) g_count[i] = 0;
    sh[t] = v;
    __syncthreads();
    for (int o = 1; o < SCAN_BLK; o <<= 1) {
        int a = (t >= o) ? sh[t - o] : 0;
        __syncthreads();
        sh[t] += a;
        __syncthreads();
    }
    if (i < N_ALL) g_start[i] = sh[t] - v;
    if (t == SCAN_BLK - 1) g_bsum[blockIdx.x] = sh[t];
}

// scan stage 2: parallel exclusive scan of 147 block sums
__global__ void scan2_kernel() {
    __shared__ int sh[256];
    int t = threadIdx.x;
    int v = (t < N_SCAN_BLOCKS) ? g_bsum[t] : 0;
    sh[t] = v;
    __syncthreads();
    for (int o = 1; o < 256; o <<= 1) {
        int a = (t >= o) ? sh[t - o] : 0;
        __syncthreads();
        sh[t] += a;
        __syncthreads();
    }
    if (t < N_SCAN_BLOCKS) g_bsum[t] = sh[t] - v;
}

// scan stage 3: add block offsets; init cursors; sentinel
__global__ void scan3_kernel() {
    int i = blockIdx.x * SCAN_BLK + threadIdx.x;
    if (i < N_ALL) {
        int s = g_start[i] + g_bsum[blockIdx.x];
        g_start[i]  = s;
        g_cursor[i] = s;
    }
    if (i == 0) g_start[N_ALL] = N_EDGES;
}

// ---------------------------------------------------------------------------
// scatter edges into CSR order
// ---------------------------------------------------------------------------
__global__ void scatter_kernel(const int*   __restrict__ rows,
                               const int*   __restrict__ cols,
                               const float* __restrict__ vals) {
    int e = blockIdx.x * blockDim.x + threadIdx.x;
    if (e >= N_EDGES) return;
    int r = __ldg(rows + e);
    int pos = atomicAdd(&g_cursor[r], 1);
    g_epack[pos] = make_int2(__ldg(cols + e), __float_as_int(__ldg(vals + e)));
}

// ---------------------------------------------------------------------------
// SpMM core: warp per row, 8 lanes per edge (16 B each), lane = g*8+sl.
// Measured-optimal loop: single accumulator set, 4-edge chunks, unroll 2.
// ---------------------------------------------------------------------------
__device__ __forceinline__ void edge_accum(const __half* __restrict__ hx,
                                           int2 p, int sl, float acc[8]) {
    float v = __int_as_float(p.y);
    uint4 q = __ldg((const uint4*)(hx + (size_t)p.x * DIM) + sl);
    float2 f;
    f = __half22float2(*(__half2*)&q.x); acc[0] += v * f.x; acc[1] += v * f.y;
    f = __half22float2(*(__half2*)&q.y); acc[2] += v * f.x; acc[3] += v * f.y;
    f = __half22float2(*(__half2*)&q.z); acc[4] += v * f.x; acc[5] += v * f.y;
    f = __half22float2(*(__half2*)&q.w); acc[6] += v * f.x; acc[7] += v * f.y;
}

__device__ __forceinline__ void spmm_row(const __half* __restrict__ hx,
                                         int s, int e, int g, int sl,
                                         float acc[8]) {
#pragma unroll
    for (int k = 0; k < 8; k++) acc[k] = 0.f;
    int n  = e - s;
    int n4 = n & ~3;
#pragma unroll 2
    for (int j = s; j < s + n4; j += 4) {
        int2 p = __ldg(&g_epack[j + g]);
        edge_accum(hx, p, sl, acc);
    }
    int rem = n - n4;
    if (g < rem) {
        int2 p = __ldg(&g_epack[s + n4 + g]);
        edge_accum(hx, p, sl, acc);
    }
#pragma unroll
    for (int k = 0; k < 8; k++) {
        acc[k] += __shfl_xor_sync(0xFFFFFFFFu, acc[k], 8);
        acc[k] += __shfl_xor_sync(0xFFFFFFFFu, acc[k], 16);
    }
}

__device__ __forceinline__ uint4 pack_half8(const float a[8]) {
    __half2 h[4];
    h[0] = __floats2half2_rn(a[0], a[1]);
    h[1] = __floats2half2_rn(a[2], a[3]);
    h[2] = __floats2half2_rn(a[4], a[5]);
    h[3] = __floats2half2_rn(a[6], a[7]);
    return *(uint4*)h;
}

// spmm1: e1 = spmm(embed) -> fp16 shadow
__global__ void __launch_bounds__(256) spmm1_kernel() {
    int w = (blockIdx.x * blockDim.x + threadIdx.x) >> 5;
    int lane = threadIdx.x & 31;
    if (w >= N_ALL) return;
    int g = lane >> 3, sl = lane & 7;
    float acc[8];
    spmm_row(g_hx[0], g_start[w], g_start[w + 1], g, sl, acc);
    if (g == 0)
        ((uint4*)(g_hx[1] + (size_t)w * DIM))[sl] = pack_half8(acc);
}

// spmm2: e2 = 1.875*spmm(e1) - 0.75*embed -> fp16 shadow + fp32 copy
__global__ void __launch_bounds__(256) spmm2_kernel() {
    int w = (blockIdx.x * blockDim.x + threadIdx.x) >> 5;
    int lane = threadIdx.x & 31;
    if (w >= N_ALL) return;
    int g = lane >> 3, sl = lane & 7;
    float acc[8];
    spmm_row(g_hx[1], g_start[w], g_start[w + 1], g, sl, acc);
    if (g < 2) {
        const float4* emp = (const float4*)(g_embed + (size_t)w * DIM);
        float4 em0 = emp[2 * sl], em1 = emp[2 * sl + 1];
        float r[8];
        r[0] = THETA1_K2 * acc[0] - THETA3_K2 * em0.x;
        r[1] = THETA1_K2 * acc[1] - THETA3_K2 * em0.y;
        r[2] = THETA1_K2 * acc[2] - THETA3_K2 * em0.z;
        r[3] = THETA1_K2 * acc[3] - THETA3_K2 * em0.w;
        r[4] = THETA1_K2 * acc[4] - THETA3_K2 * em1.x;
        r[5] = THETA1_K2 * acc[5] - THETA3_K2 * em1.y;
        r[6] = THETA1_K2 * acc[6] - THETA3_K2 * em1.z;
        r[7] = THETA1_K2 * acc[7] - THETA3_K2 * em1.w;
        if (g == 0) {
            ((uint4*)(g_hx[2] + (size_t)w * DIM))[sl] = pack_half8(r);
        } else {
            float4* e2p = (float4*)(g_e2f + (size_t)w * DIM);
            e2p[2 * sl]     = make_float4(r[0], r[1], r[2], r[3]);
            e2p[2 * sl + 1] = make_float4(r[4], r[5], r[6], r[7]);
        }
    }
}

// spmm3 + final epilogue:
//   bs = 0.25*(embed + 0.2*e1 + e2 + (28/15)*acc);  bp = tanh(0.1*embed - bs)
__global__ void __launch_bounds__(256) spmm3_kernel(float* __restrict__ out) {
    int w = (blockIdx.x * blockDim.x + threadIdx.x) >> 5;
    int lane = threadIdx.x & 31;
    if (w >= N_ALL) return;
    int g = lane >> 3, sl = lane & 7;
    float acc[8];
    spmm_row(g_hx[2], g_start[w], g_start[w + 1], g, sl, acc);
    if (g < 2) {
        const float4* emp = (const float4*)(g_embed + (size_t)w * DIM);
        const float4* a2p = (const float4*)(g_e2f  + (size_t)w * DIM);
        float4 em0 = emp[2 * sl], em1 = emp[2 * sl + 1];
        float4 a20 = a2p[2 * sl], a21 = a2p[2 * sl + 1];
        uint4 a1q = ((const uint4*)(g_hx[1] + (size_t)w * DIM))[sl];
        float a1[8];
        {
            float2 f;
            f = __half22float2(*(__half2*)&a1q.x); a1[0] = f.x; a1[1] = f.y;
            f = __half22float2(*(__half2*)&a1q.y); a1[2] = f.x; a1[3] = f.y;
            f = __half22float2(*(__half2*)&a1q.z); a1[4] = f.x; a1[5] = f.y;
            f = __half22float2(*(__half2*)&a1q.w); a1[6] = f.x; a1[7] = f.y;
        }
        float em[8] = {em0.x, em0.y, em0.z, em0.w, em1.x, em1.y, em1.z, em1.w};
        float a2[8] = {a20.x, a20.y, a20.z, a20.w, a21.x, a21.y, a21.z, a21.w};
        float bs[8];
#pragma unroll
        for (int k = 0; k < 8; k++)
            bs[k] = 0.25f * (em[k] + 0.2f * a1[k] + a2[k] + THETA1_K3 * acc[k]);
        float4* orow = (float4*)(out + (size_t)w * 128);
        if (g == 0) {
            orow[2 * sl]     = make_float4(bs[0], bs[1], bs[2], bs[3]);
            orow[2 * sl + 1] = make_float4(bs[4], bs[5], bs[6], bs[7]);
        } else {
            float bp[8];
#pragma unroll
            for (int k = 0; k < 8; k++)
                bp[k] = tanhf(0.1f * em[k] - bs[k]);
            orow[16 + 2 * sl] = make_float4(bp[0], bp[1], bp[2], bp[3]);
            orow[17 + 2 * sl] = make_float4(bp[4], bp[5], bp[6], bp[7]);
        }
    }
}

// ---------------------------------------------------------------------------
extern "C" void kernel_launch(void* const* d_in, const int* in_sizes, int n_in,
                              void* d_out, int out_size) {
    const float* user = (const float*)d_in[0];
    const float* item = (const float*)d_in[1];
    const int*   rows = (const int*)d_in[2];
    const int*   cols = (const int*)d_in[3];
    const float* vals = (const float*)d_in[4];
    float* out = (float*)d_out;

    const int TPB = 256;
    const int init_blocks = (NELEM / 4 + TPB - 1) / TPB;
    const int edge_blocks = (N_EDGES + TPB - 1) / TPB;
    const int spmm_blocks = ((N_ALL * 32) + TPB - 1) / TPB;

    init_kernel<<<init_blocks, TPB>>>(user, item, rows);
    scan1_kernel<<<N_SCAN_BLOCKS, SCAN_BLK>>>();
    scan2_kernel<<<1, 256>>>();
    scan3_kernel<<<N_SCAN_BLOCKS, SCAN_BLK>>>();
    scatter_kernel<<<edge_blocks, TPB>>>(rows, cols, vals);
    spmm1_kernel<<<spmm_blocks, TPB>>>();
    spmm2_kernel<<<spmm_blocks, TPB>>>();
    spmm3_kernel<<<spmm_blocks, TPB>>>(out);
}